// round 2
// baseline (speedup 1.0000x reference)
#include <cuda_runtime.h>

#define NSEQ 4096
#define NFFT 8192
#define PI_F 3.141592653589793f

// -------- scratch (no allocations allowed) --------
__device__ float4 g_PQrev[256 * 4096];   // per (h,dpair): P,Q at f=rev12(m), bit-rev order, 16.8 MB
__device__ float4 g_PQnyq[256];          // P,Q at Nyquist f=4096
__device__ float  g_xt[64 * 64 * 4096];  // [bh][d][t] transposed x / y (in-place), 67 MB

static __device__ __forceinline__ int pidx(int n) { return n + (n >> 5); }
#define SMEM_CNT  (NFFT - 1 + ((NFFT - 1) >> 5) + 1)   /* 8447 */
#define SMEM_BYTES (SMEM_CNT * 8)

static __device__ __forceinline__ float2 cadd(float2 a, float2 b) { return make_float2(a.x + b.x, a.y + b.y); }
static __device__ __forceinline__ float2 csub(float2 a, float2 b) { return make_float2(a.x - b.x, a.y - b.y); }
static __device__ __forceinline__ float2 cmul(float2 a, float2 b) {
    return make_float2(fmaf(a.x, b.x, -a.y * b.y), fmaf(a.x, b.y, a.y * b.x));
}
static __device__ __forceinline__ float2 cconj(float2 a) { return make_float2(a.x, -a.y); }

// exp(SGN * i * pi * k / 8), k = 0..7
template <int SGN>
static __device__ __forceinline__ float2 rt16(int k) {
    const float C[8] = {1.f, 0.92387953251f, 0.70710678119f, 0.38268343236f,
                        0.f, -0.38268343236f, -0.70710678119f, -0.92387953251f};
    const float S[8] = {0.f, 0.38268343236f, 0.70710678119f, 0.92387953251f,
                        1.f, 0.92387953251f, 0.70710678119f, 0.38268343236f};
    return make_float2(C[k], (float)SGN * S[k]);
}

// One register round of 4 radix-2 stages on 16 elements.
// Forward (SGN=-1): DIF stages with spans (8,4,2,1)*stride; twiddle = base^(2^s) * roots.
// Inverse (SGN=+1): mirrored DIT stages in reverse order with conjugate twiddles.
// ang = pi * w / S0 (positive magnitude).
template <int SGN>
static __device__ __forceinline__ void fft_round(float2 r[16], float ang) {
    float sv, cv;
    __sincosf(ang, &sv, &cv);
    float2 b1 = make_float2(cv, SGN < 0 ? -sv : sv);
    float2 b2 = cmul(b1, b1), b4 = cmul(b2, b2), b8 = cmul(b4, b4);
    float2 tw8[8], tw4[4], tw2[2];
#pragma unroll
    for (int k = 0; k < 8; k++) tw8[k] = cmul(b1, rt16<SGN>(k));
#pragma unroll
    for (int k = 0; k < 4; k++) tw4[k] = cmul(b2, rt16<SGN>(2 * k));
    tw2[0] = b4;
    tw2[1] = cmul(b4, make_float2(0.f, (float)SGN));
    if (SGN < 0) {
#pragma unroll
        for (int k = 0; k < 8; k++) { float2 u = r[k], v = r[k + 8]; r[k] = cadd(u, v); r[k + 8] = cmul(csub(u, v), tw8[k]); }
#pragma unroll
        for (int g = 0; g < 16; g += 8)
#pragma unroll
            for (int c = 0; c < 4; c++) { int a = g + c; float2 u = r[a], v = r[a + 4]; r[a] = cadd(u, v); r[a + 4] = cmul(csub(u, v), tw4[c]); }
#pragma unroll
        for (int g = 0; g < 16; g += 4)
#pragma unroll
            for (int c = 0; c < 2; c++) { int a = g + c; float2 u = r[a], v = r[a + 2]; r[a] = cadd(u, v); r[a + 2] = cmul(csub(u, v), tw2[c]); }
#pragma unroll
        for (int a = 0; a < 16; a += 2) { float2 u = r[a], v = r[a + 1]; r[a] = cadd(u, v); r[a + 1] = cmul(csub(u, v), b8); }
    } else {
#pragma unroll
        for (int a = 0; a < 16; a += 2) { float2 v = cmul(r[a + 1], b8), u = r[a]; r[a] = cadd(u, v); r[a + 1] = csub(u, v); }
#pragma unroll
        for (int g = 0; g < 16; g += 4)
#pragma unroll
            for (int c = 0; c < 2; c++) { int a = g + c; float2 v = cmul(r[a + 2], tw2[c]), u = r[a]; r[a] = cadd(u, v); r[a + 2] = csub(u, v); }
#pragma unroll
        for (int g = 0; g < 16; g += 8)
#pragma unroll
            for (int c = 0; c < 4; c++) { int a = g + c; float2 v = cmul(r[a + 4], tw4[c]), u = r[a]; r[a] = cadd(u, v); r[a + 4] = csub(u, v); }
#pragma unroll
        for (int k = 0; k < 8; k++) { float2 v = cmul(r[k + 8], tw8[k]), u = r[k]; r[k] = cadd(u, v); r[k + 8] = csub(u, v); }
    }
}

// Forward DIF spans 4096..2 (12 stages). r preloaded with natural positions tid+512k.
// Leaves pre-final-stage values in smem; final span-1 stage is fused into the caller.
static __device__ __forceinline__ void fwd_rounds(float2* sm, float2 r[16], int tid) {
    fft_round<-1>(r, PI_F * (1.0f / 4096.0f) * (float)tid);
#pragma unroll
    for (int k = 0; k < 16; k++) sm[pidx(tid + 512 * k)] = r[k];
    __syncthreads();
    int w2 = tid & 31, blk = tid >> 5;
#pragma unroll
    for (int k = 0; k < 16; k++) r[k] = sm[pidx(blk * 512 + w2 + 32 * k)];
    fft_round<-1>(r, PI_F * (1.0f / 256.0f) * (float)w2);
#pragma unroll
    for (int k = 0; k < 16; k++) sm[pidx(blk * 512 + w2 + 32 * k)] = r[k];
    __syncthreads();
    int w3 = tid & 1, sub = tid >> 1;
#pragma unroll
    for (int k = 0; k < 16; k++) r[k] = sm[pidx(sub * 32 + w3 + 2 * k)];
    fft_round<-1>(r, PI_F * (1.0f / 16.0f) * (float)w3);
#pragma unroll
    for (int k = 0; k < 16; k++) sm[pidx(sub * 32 + w3 + 2 * k)] = r[k];
    __syncthreads();
}

// ---------------- K1: kernel spectra P,Q per (h, dpair) ----------------
__global__ __launch_bounds__(512) void k1_spectra(const float* __restrict__ zero,
                                                  const float* __restrict__ pos,
                                                  const float* __restrict__ gamma) {
    extern __shared__ float2 sm[];
    int tid = threadIdx.x;
    int h = blockIdx.x >> 5, dp = blockIdx.x & 31;
    int d0 = 2 * dp, d1 = d0 + 1;
    float lg0 = logf(gamma[h * 64 + d0]);
    float lg1 = logf(gamma[h * 64 + d1]);

    float2 r[16];
#pragma unroll
    for (int k = 0; k < 8; k++) {
        int t = tid + 512 * k;
        float v0, v1;
        if (t == 0) {
            v0 = zero[h * 64 + d0];
            v1 = zero[h * 64 + d1];
        } else {
            const float* pp = pos + ((size_t)h * 4095 + (t - 1)) * 64;
            v0 = fmaf((float)t, lg0, pp[d0]);
            v1 = fmaf((float)t, lg1, pp[d1]);
        }
        v0 = fminf(fmaxf(v0, -60.f), 30.f);
        v1 = fminf(fmaxf(v1, -60.f), 30.f);
        r[k] = make_float2(expf(v0), expf(v1));
    }
#pragma unroll
    for (int k = 8; k < 16; k++) r[k] = make_float2(0.f, 0.f);

    fwd_rounds(sm, r, tid);

    // Final span-1 butterfly + conj-symmetry unpack + store P,Q (bit-rev order).
    float4* pq = g_PQrev + ((size_t)(h * 32 + dp) << 12);
    const float sc = 0.5f / 8192.0f;  // fold 1/2 unpack and 1/N inverse scale
#pragma unroll
    for (int i = 0; i < 8; i++) {
        int m = tid + 512 * i;
        float2 Za = sm[pidx(2 * m)], Zb = sm[pidx(2 * m + 1)];
        float2 Zf1 = cadd(Za, Zb);
        float2 Zg2c;  // conj(Z[N - f1])
        if (m == 0) {
            Zg2c = cconj(Zf1);
            float2 Zn = csub(Za, Zb);  // Z[4096]; N-4096 = 4096 (self)
            float A0n = Zn.x, A1n = Zn.y;
            g_PQnyq[h * 32 + dp] = make_float4((A0n + A1n) * sc, 0.f, (A0n - A1n) * sc, 0.f);
        } else {
            int f1 = __brev(m) >> 20;                 // rev12(m)
            int mp = __brev(4096 - f1) >> 20;         // partner pair index
            float2 Zc = sm[pidx(2 * mp)], Zd = sm[pidx(2 * mp + 1)];
            Zg2c = cconj(csub(Zc, Zd));               // conj(Z[8192 - f1])
        }
        float2 Ssum = cadd(Zf1, Zg2c);
        float2 Sdif = csub(Zf1, Zg2c);
        float2 A0 = make_float2(0.5f * Ssum.x, 0.5f * Ssum.y);
        float2 A1 = make_float2(0.5f * Sdif.y, -0.5f * Sdif.x);  // -i * Sdif / 2
        pq[m] = make_float4((A0.x + A1.x) * sc, (A0.y + A1.y) * sc,
                            (A0.x - A1.x) * sc, (A0.y - A1.y) * sc);
    }
}

// ---------------- K2: x [bh][t][d] -> g_xt [bh][d][t] ----------------
__global__ void k2_transpose(const float* __restrict__ x) {
    __shared__ float tile[32][33];
    int bh = blockIdx.z;
    int t0 = blockIdx.x << 5, d0 = blockIdx.y << 5;
    const float* xp = x + (size_t)bh * (4096 * 64);
    float* xtp = g_xt + (size_t)bh * (64 * 4096);
    int tx = threadIdx.x, ty = threadIdx.y;
#pragma unroll
    for (int j = 0; j < 32; j += 8) tile[ty + j][tx] = xp[(size_t)(t0 + ty + j) * 64 + d0 + tx];
    __syncthreads();
#pragma unroll
    for (int j = 0; j < 32; j += 8) xtp[(size_t)(d0 + ty + j) * 4096 + t0 + tx] = tile[tx][ty + j];
}

// ---------------- K3: per (b,h,dpair) FFT -> multiply -> IFFT, in place ----------------
__global__ __launch_bounds__(512) void k3_fftconv() {
    extern __shared__ float2 sm[];
    int tid = threadIdx.x;
    int bh = blockIdx.x >> 5, dp = blockIdx.x & 31;
    int h = bh & 7;
    float* row0 = g_xt + (size_t)(bh * 64 + 2 * dp) * 4096;
    float* row1 = row0 + 4096;

    float2 r[16];
#pragma unroll
    for (int k = 0; k < 8; k++) { int t = tid + 512 * k; r[k] = make_float2(row0[t], row1[t]); }
#pragma unroll
    for (int k = 8; k < 16; k++) r[k] = make_float2(0.f, 0.f);

    fwd_rounds(sm, r, tid);

    // MID: final fwd stage + pointwise (P,Q) + first inverse stage, fused.
    const float4* pq = g_PQrev + ((size_t)(h * 32 + dp) << 12);
    float2 wlo[8], whi[8];
#pragma unroll
    for (int i = 0; i < 8; i++) {
        int m = tid + 512 * i;
        float2 Za = sm[pidx(2 * m)], Zb = sm[pidx(2 * m + 1)];
        float2 Zf1 = cadd(Za, Zb), Zf2 = csub(Za, Zb);
        if (m == 0) {
            float4 p0 = pq[0];
            float4 pn = g_PQnyq[h * 32 + dp];
            float2 P0 = make_float2(p0.x, p0.y), Q0 = make_float2(p0.z, p0.w);
            float2 Pn = make_float2(pn.x, pn.y), Qn = make_float2(pn.z, pn.w);
            wlo[i] = cadd(cmul(Zf1, P0), cmul(cconj(Zf1), Q0));   // W[0]
            whi[i] = cadd(cmul(Zf2, Pn), cmul(cconj(Zf2), Qn));   // W[4096]
        } else {
            int f1 = __brev(m) >> 20;
            int mp = __brev(4096 - f1) >> 20;
            float2 Zc = sm[pidx(2 * mp)], Zd = sm[pidx(2 * mp + 1)];
            float2 Zg1 = cadd(Zc, Zd), Zg2 = csub(Zc, Zd);
            float4 q1 = pq[m], q2 = pq[mp];
            float2 P1 = make_float2(q1.x, q1.y), Q1 = make_float2(q1.z, q1.w);
            float2 P2 = make_float2(q2.x, q2.y), Q2 = make_float2(q2.z, q2.w);
            // W[f]  = Z[f] P[f] + conj(Z[N-f]) Q[f];  P,Q conj-symmetric
            wlo[i] = cadd(cmul(Zf1, P1), cmul(cconj(Zg2), Q1));            // W[f1]
            whi[i] = cadd(cmul(Zf2, cconj(P2)), cmul(cconj(Zg1), cconj(Q2)));  // W[f1+4096]
        }
    }
    __syncthreads();
#pragma unroll
    for (int i = 0; i < 8; i++) {  // first inverse DIT stage (span 1, tw = 1)
        int m = tid + 512 * i;
        sm[pidx(2 * m)]     = cadd(wlo[i], whi[i]);
        sm[pidx(2 * m + 1)] = csub(wlo[i], whi[i]);
    }
    __syncthreads();

    // Inverse DIT spans 2..4096 (mirrored rounds).
    int w3 = tid & 1, sub = tid >> 1;
#pragma unroll
    for (int k = 0; k < 16; k++) r[k] = sm[pidx(sub * 32 + w3 + 2 * k)];
    fft_round<1>(r, PI_F * (1.0f / 16.0f) * (float)w3);
#pragma unroll
    for (int k = 0; k < 16; k++) sm[pidx(sub * 32 + w3 + 2 * k)] = r[k];
    __syncthreads();
    int w2 = tid & 31, blk = tid >> 5;
#pragma unroll
    for (int k = 0; k < 16; k++) r[k] = sm[pidx(blk * 512 + w2 + 32 * k)];
    fft_round<1>(r, PI_F * (1.0f / 256.0f) * (float)w2);
#pragma unroll
    for (int k = 0; k < 16; k++) sm[pidx(blk * 512 + w2 + 32 * k)] = r[k];
    __syncthreads();
#pragma unroll
    for (int k = 0; k < 16; k++) r[k] = sm[pidx(tid + 512 * k)];
    fft_round<1>(r, PI_F * (1.0f / 4096.0f) * (float)tid);
#pragma unroll
    for (int k = 0; k < 8; k++) {  // natural order; keep t < 4096 only
        int t = tid + 512 * k;
        row0[t] = r[k].x;
        row1[t] = r[k].y;
    }
}

// ---------------- K4: g_xt (y) [bh][d][t] -> out [bh][t][d] ----------------
__global__ void k4_transpose(float* __restrict__ out) {
    __shared__ float tile[32][33];
    int bh = blockIdx.z;
    int t0 = blockIdx.x << 5, d0 = blockIdx.y << 5;
    const float* ytp = g_xt + (size_t)bh * (64 * 4096);
    float* op = out + (size_t)bh * (4096 * 64);
    int tx = threadIdx.x, ty = threadIdx.y;
#pragma unroll
    for (int j = 0; j < 32; j += 8) tile[ty + j][tx] = ytp[(size_t)(d0 + ty + j) * 4096 + t0 + tx];
    __syncthreads();
#pragma unroll
    for (int j = 0; j < 32; j += 8) op[(size_t)(t0 + ty + j) * 64 + d0 + tx] = tile[tx][ty + j];
}

extern "C" void kernel_launch(void* const* d_in, const int* in_sizes, int n_in,
                              void* d_out, int out_size) {
    (void)in_sizes; (void)n_in; (void)out_size;
    const float* x     = (const float*)d_in[0];
    const float* zero  = (const float*)d_in[1];
    const float* pos   = (const float*)d_in[2];
    const float* gamma = (const float*)d_in[3];
    float* out = (float*)d_out;

    cudaFuncSetAttribute(k1_spectra, cudaFuncAttributeMaxDynamicSharedMemorySize, SMEM_BYTES);
    cudaFuncSetAttribute(k3_fftconv, cudaFuncAttributeMaxDynamicSharedMemorySize, SMEM_BYTES);

    k1_spectra<<<256, 512, SMEM_BYTES>>>(zero, pos, gamma);
    dim3 tb(32, 8);
    k2_transpose<<<dim3(128, 2, 64), tb>>>(x);
    k3_fftconv<<<2048, 512, SMEM_BYTES>>>();
    k4_transpose<<<dim3(128, 2, 64), tb>>>(out);
}

// round 3
// speedup vs baseline: 1.2013x; 1.2013x over previous
#include <cuda_runtime.h>

#define PI_F 3.14159265358979f

// -------- scratch (no device allocations allowed) --------
__device__ float4 g_Apair[512 * 4096];   // per (h,d): (A[rev(m)], A[rev(mp)]) scaled, 33.6 MB
__device__ float  g_Anyq[512];           // A[4096] (real) per channel, scaled
__device__ float  g_xt[64 * 64 * 4096];  // [bh][d][t] transposed x / y (in-place), 67 MB

static __device__ __forceinline__ int pidx(int n) { return n + (n >> 4); }
#define SMEM_CNT 4352   /* pidx(4095)=4350 */

static __device__ __forceinline__ float2 cadd(float2 a, float2 b) { return make_float2(a.x + b.x, a.y + b.y); }
static __device__ __forceinline__ float2 csub(float2 a, float2 b) { return make_float2(a.x - b.x, a.y - b.y); }
static __device__ __forceinline__ float2 cmul(float2 a, float2 b) {
    return make_float2(fmaf(a.x, b.x, -a.y * b.y), fmaf(a.x, b.y, a.y * b.x));
}
static __device__ __forceinline__ float2 cconj(float2 a) { return make_float2(a.x, -a.y); }

// exp(SGN * i * pi * k / 8), k = 0..7
template <int SGN>
static __device__ __forceinline__ float2 rt16(int k) {
    const float C[8] = {1.f, 0.92387953251f, 0.70710678119f, 0.38268343236f,
                        0.f, -0.38268343236f, -0.70710678119f, -0.92387953251f};
    const float S[8] = {0.f, 0.38268343236f, 0.70710678119f, 0.92387953251f,
                        1.f, 0.92387953251f, 0.70710678119f, 0.38268343236f};
    return make_float2(C[k], (float)SGN * S[k]);
}

// One register round of 4 radix-2 stages on 16 elements.
// Forward (SGN=-1): DIF spans (8,4,2,1)*stride. Inverse (SGN=+1): DIT mirrored.
// TRIV: twiddle base = 1 (compile-time constant roots only).
template <int SGN, bool TRIV>
static __device__ __forceinline__ void fft_round(float2 r[16], float ang) {
    float2 b1;
    if (TRIV) {
        b1 = make_float2(1.f, 0.f);
    } else {
        float sv, cv;
        __sincosf(ang, &sv, &cv);
        b1 = make_float2(cv, SGN < 0 ? -sv : sv);
    }
    float2 b2 = cmul(b1, b1), b4 = cmul(b2, b2), b8 = cmul(b4, b4);
    float2 tw8[8], tw4[4], tw2[2];
#pragma unroll
    for (int k = 0; k < 8; k++) tw8[k] = cmul(b1, rt16<SGN>(k));
#pragma unroll
    for (int k = 0; k < 4; k++) tw4[k] = cmul(b2, rt16<SGN>(2 * k));
    tw2[0] = b4;
    tw2[1] = cmul(b4, make_float2(0.f, (float)SGN));
    if (SGN < 0) {
#pragma unroll
        for (int k = 0; k < 8; k++) { float2 u = r[k], v = r[k + 8]; r[k] = cadd(u, v); r[k + 8] = cmul(csub(u, v), tw8[k]); }
#pragma unroll
        for (int g = 0; g < 16; g += 8)
#pragma unroll
            for (int c = 0; c < 4; c++) { int a = g + c; float2 u = r[a], v = r[a + 4]; r[a] = cadd(u, v); r[a + 4] = cmul(csub(u, v), tw4[c]); }
#pragma unroll
        for (int g = 0; g < 16; g += 4)
#pragma unroll
            for (int c = 0; c < 2; c++) { int a = g + c; float2 u = r[a], v = r[a + 2]; r[a] = cadd(u, v); r[a + 2] = cmul(csub(u, v), tw2[c]); }
#pragma unroll
        for (int a = 0; a < 16; a += 2) { float2 u = r[a], v = r[a + 1]; r[a] = cadd(u, v); r[a + 1] = cmul(csub(u, v), b8); }
    } else {
#pragma unroll
        for (int a = 0; a < 16; a += 2) { float2 v = cmul(r[a + 1], b8), u = r[a]; r[a] = cadd(u, v); r[a + 1] = csub(u, v); }
#pragma unroll
        for (int g = 0; g < 16; g += 4)
#pragma unroll
            for (int c = 0; c < 2; c++) { int a = g + c; float2 v = cmul(r[a + 2], tw2[c]), u = r[a]; r[a] = cadd(u, v); r[a + 2] = csub(u, v); }
#pragma unroll
        for (int g = 0; g < 16; g += 8)
#pragma unroll
            for (int c = 0; c < 4; c++) { int a = g + c; float2 v = cmul(r[a + 4], tw4[c]), u = r[a]; r[a] = cadd(u, v); r[a + 4] = csub(u, v); }
#pragma unroll
        for (int k = 0; k < 8; k++) { float2 v = cmul(r[k + 8], tw8[k]), u = r[k]; r[k] = cadd(u, v); r[k + 8] = csub(u, v); }
    }
}

// Forward 4096-pt DIF (12 stages = 3 rounds), natural -> bit-reversed in smem.
// r preloaded with positions tid + 256k.
static __device__ __forceinline__ void fft4096_fwd(float2* sm, float2 r[16], int tid) {
    fft_round<-1, false>(r, PI_F * (1.0f / 2048.0f) * (float)tid);
#pragma unroll
    for (int k = 0; k < 16; k++) sm[pidx(tid + 256 * k)] = r[k];
    __syncthreads();
    int w = tid & 15, blk = tid >> 4;
#pragma unroll
    for (int k = 0; k < 16; k++) r[k] = sm[pidx(blk * 256 + w + 16 * k)];
    fft_round<-1, false>(r, PI_F * (1.0f / 128.0f) * (float)w);
#pragma unroll
    for (int k = 0; k < 16; k++) sm[pidx(blk * 256 + w + 16 * k)] = r[k];
    __syncthreads();
#pragma unroll
    for (int k = 0; k < 16; k++) r[k] = sm[pidx(tid * 16 + k)];
    fft_round<-1, true>(r, 0.f);
#pragma unroll
    for (int k = 0; k < 16; k++) sm[pidx(tid * 16 + k)] = r[k];
    __syncthreads();
}

// ---------------- K1: kernel spectrum table per (h, d) ----------------
__global__ __launch_bounds__(256) void k1_spectra(const float* __restrict__ zero,
                                                  const float* __restrict__ pos,
                                                  const float* __restrict__ gamma) {
    __shared__ float2 sm[SMEM_CNT];
    int tid = threadIdx.x;
    int ch = blockIdx.x;          // h*64 + d
    int h = ch >> 6, d = ch & 63;
    float lg = logf(gamma[ch]);
    float z0 = zero[ch];
    float e0 = expf(fminf(fmaxf(z0, -60.f), 30.f));

    float2 r[16];
#pragma unroll
    for (int k = 0; k < 16; k++) {
        int m = tid + 256 * k;
        float v0 = 0.f, v1 = 0.f;
        if (k < 8) {
            int t0 = 2 * m, t1 = 2 * m + 1;
            if (t0 == 0) v0 = e0;
            else {
                float p = pos[((size_t)h * 4095 + (t0 - 1)) * 64 + d];
                v0 = expf(fminf(fmaxf(fmaf((float)t0, lg, p), -60.f), 30.f));
            }
            if (t1 <= 4095) {
                float p = pos[((size_t)h * 4095 + (t1 - 1)) * 64 + d];
                v1 = expf(fminf(fmaxf(fmaf((float)t1, lg, p), -60.f), 30.f));
            }
        } else if (m == 2048) {
            v0 = e0;  // a[4096] = exp(clip(zero))
        }
        r[k] = make_float2(v0, v1);
    }

    fft4096_fwd(sm, r, tid);

    // Unpack real-FFT: A[kf] = (S + T2)/2, store scaled by 1/16384 -> /32768
    const float sc = 1.0f / 32768.0f;
    float2 ar[16];
#pragma unroll
    for (int k = 0; k < 16; k++) {
        int m = tid + 256 * k;
        int kf = __brev(m) >> 20;
        int mp = __brev((4096 - kf) & 4095) >> 20;
        float2 Zm = sm[pidx(m)], Zp = sm[pidx(mp)];
        float2 S = cadd(Zm, cconj(Zp));
        float2 D = csub(Zm, cconj(Zp));
        float sw, cw;
        __sincosf(PI_F * (1.0f / 4096.0f) * (float)kf, &sw, &cw);
        float2 W = make_float2(cw, -sw);
        float2 T = cmul(W, D);
        float2 T2 = make_float2(T.y, -T.x);       // -i*W*D
        float2 Vlo = cadd(S, T2);                 // = 2*A[kf]
        ar[k] = make_float2(Vlo.x * sc, Vlo.y * sc);
        if (m == 0) {
            float2 Vhi = csub(S, T2);             // = 2*A[4096] (real)
            g_Anyq[ch] = Vhi.x * sc;
        }
    }
    __syncthreads();
#pragma unroll
    for (int k = 0; k < 16; k++) sm[pidx(tid + 256 * k)] = ar[k];
    __syncthreads();
    float4* ap = g_Apair + (size_t)ch * 4096;
#pragma unroll
    for (int k = 0; k < 16; k++) {
        int m = tid + 256 * k;
        int kf = __brev(m) >> 20;
        int mp = __brev((4096 - kf) & 4095) >> 20;
        float2 a0 = sm[pidx(m)], a1 = sm[pidx(mp)];
        ap[m] = make_float4(a0.x, a0.y, a1.x, a1.y);
    }
}

// ---------------- K2: x [bh][t][d] -> g_xt [bh][d][t] ----------------
__global__ void k2_transpose(const float* __restrict__ x) {
    __shared__ float tile[32][33];
    int bh = blockIdx.z;
    int t0 = blockIdx.x << 5, d0 = blockIdx.y << 5;
    const float* xp = x + (size_t)bh * (4096 * 64);
    float* xtp = g_xt + (size_t)bh * (64 * 4096);
    int tx = threadIdx.x, ty = threadIdx.y;
#pragma unroll
    for (int j = 0; j < 32; j += 8) tile[ty + j][tx] = xp[(size_t)(t0 + ty + j) * 64 + d0 + tx];
    __syncthreads();
#pragma unroll
    for (int j = 0; j < 32; j += 8) xtp[(size_t)(d0 + ty + j) * 4096 + t0 + tx] = tile[tx][ty + j];
}

// ---------------- K3: per (bh, d) real FFT conv via packed 4096-pt complex FFT ----------------
__global__ __launch_bounds__(256, 3) void k3_fftconv() {
    __shared__ float2 sm[SMEM_CNT];
    int tid = threadIdx.x;
    int bhd = blockIdx.x;                 // bh*64 + d
    int ch = ((bhd >> 6) & 7) * 64 + (bhd & 63);  // (h, d) channel for table
    float2* row = (float2*)(g_xt + (size_t)bhd * 4096);

    float2 r[16];
#pragma unroll
    for (int k = 0; k < 8; k++) r[k] = row[tid + 256 * k];      // z[m]=u[2m]+i u[2m+1]
#pragma unroll
    for (int k = 8; k < 16; k++) r[k] = make_float2(0.f, 0.f);  // zero padding

    fft4096_fwd(sm, r, tid);

    // MID: unpack real-FFT, multiply with kernel spectrum, repack. All scales folded into A.
    const float4* ap = g_Apair + (size_t)ch * 4096;
    float anyq = g_Anyq[ch];
#pragma unroll
    for (int k = 0; k < 16; k++) {
        int m = tid + 256 * k;
        int kf = __brev(m) >> 20;
        int mp = __brev((4096 - kf) & 4095) >> 20;
        float2 Zm = sm[pidx(m)], Zp = sm[pidx(mp)];
        float2 S = cadd(Zm, cconj(Zp));           // 2E
        float2 D = csub(Zm, cconj(Zp));           // 2iO
        float sw, cw;
        __sincosf(PI_F * (1.0f / 4096.0f) * (float)kf, &sw, &cw);
        float2 W = make_float2(cw, -sw);
        float2 T = cmul(W, D);
        float2 T2 = make_float2(T.y, -T.x);       // -i*W*D = 2*W*O
        float2 Vlo = cadd(S, T2);                 // 2*V[kf]
        float2 Vhi = csub(S, T2);                 // 2*V[kf+4096]
        float4 A = ap[m];
        float2 Alo = make_float2(A.x, A.y);
        float2 Ahi = (m == 0) ? make_float2(anyq, 0.f) : make_float2(A.z, -A.w);  // conj(A[partner])
        float2 Ylo = cmul(Vlo, Alo);
        float2 Yhi = cmul(Vhi, Ahi);
        float2 Sum = cadd(Ylo, Yhi);
        float2 Dif = csub(Ylo, Yhi);
        float2 U = cmul(cconj(W), Dif);
        r[k] = make_float2(Sum.x - U.y, Sum.y + U.x);   // Z'[kf] = Sum + i*U (all scales folded)
    }
    __syncthreads();
#pragma unroll
    for (int k = 0; k < 16; k++) sm[pidx(tid + 256 * k)] = r[k];
    __syncthreads();

    // Inverse DIT (bit-rev -> natural), mirrored rounds.
#pragma unroll
    for (int k = 0; k < 16; k++) r[k] = sm[pidx(tid * 16 + k)];
    fft_round<1, true>(r, 0.f);
#pragma unroll
    for (int k = 0; k < 16; k++) sm[pidx(tid * 16 + k)] = r[k];
    __syncthreads();
    int w = tid & 15, blk = tid >> 4;
#pragma unroll
    for (int k = 0; k < 16; k++) r[k] = sm[pidx(blk * 256 + w + 16 * k)];
    fft_round<1, false>(r, PI_F * (1.0f / 128.0f) * (float)w);
#pragma unroll
    for (int k = 0; k < 16; k++) sm[pidx(blk * 256 + w + 16 * k)] = r[k];
    __syncthreads();
#pragma unroll
    for (int k = 0; k < 16; k++) r[k] = sm[pidx(tid + 256 * k)];
    fft_round<1, false>(r, PI_F * (1.0f / 2048.0f) * (float)tid);
#pragma unroll
    for (int k = 0; k < 8; k++) row[tid + 256 * k] = r[k];   // y[2m], y[2m+1]; t<4096 only
}

// ---------------- K4: g_xt (y) [bh][d][t] -> out [bh][t][d] ----------------
__global__ void k4_transpose(float* __restrict__ out) {
    __shared__ float tile[32][33];
    int bh = blockIdx.z;
    int t0 = blockIdx.x << 5, d0 = blockIdx.y << 5;
    const float* ytp = g_xt + (size_t)bh * (64 * 4096);
    float* op = out + (size_t)bh * (4096 * 64);
    int tx = threadIdx.x, ty = threadIdx.y;
#pragma unroll
    for (int j = 0; j < 32; j += 8) tile[ty + j][tx] = ytp[(size_t)(d0 + ty + j) * 4096 + t0 + tx];
    __syncthreads();
#pragma unroll
    for (int j = 0; j < 32; j += 8) op[(size_t)(t0 + ty + j) * 64 + d0 + tx] = tile[tx][ty + j];
}

extern "C" void kernel_launch(void* const* d_in, const int* in_sizes, int n_in,
                              void* d_out, int out_size) {
    (void)in_sizes; (void)n_in; (void)out_size;
    const float* x     = (const float*)d_in[0];
    const float* zero  = (const float*)d_in[1];
    const float* pos   = (const float*)d_in[2];
    const float* gamma = (const float*)d_in[3];
    float* out = (float*)d_out;

    k1_spectra<<<512, 256>>>(zero, pos, gamma);
    dim3 tb(32, 8);
    k2_transpose<<<dim3(128, 2, 64), tb>>>(x);
    k3_fftconv<<<4096, 256>>>();
    k4_transpose<<<dim3(128, 2, 64), tb>>>(out);
}

// round 4
// speedup vs baseline: 1.3032x; 1.0848x over previous
#include <cuda_runtime.h>

#define PI_F 3.14159265358979f

// -------- scratch (no device allocations allowed) --------
__device__ float4 g_AB[512 * 4096];      // per (h,d): (alpha, beta) per m (bit-rev order), 33.6 MB
__device__ float  g_xt[64 * 64 * 4096];  // [bh][d][t] transposed x / y (in-place), 67 MB

static __device__ __forceinline__ int pidx(int n) { return n + (n >> 4); }
#define SMEM_CNT 4352   /* pidx(4095)=4350 */

// ---- packed f32x2 helpers (Blackwell) ----
union F2U { float2 f; unsigned long long u; };

static __device__ __forceinline__ float2 cadd(float2 a, float2 b) {
    F2U x, y, r; x.f = a; y.f = b;
    asm("add.rn.f32x2 %0, %1, %2;" : "=l"(r.u) : "l"(x.u), "l"(y.u));
    return r.f;
}
static __device__ __forceinline__ float2 csub(float2 a, float2 b) {
    // a - b == fma(b, -1, a), exact
    F2U x, y, r; x.f = a; y.f = b;
    const unsigned long long NEG1 = 0xBF800000BF800000ULL;
    asm("fma.rn.f32x2 %0, %1, %2, %3;" : "=l"(r.u) : "l"(y.u), "l"(NEG1), "l"(x.u));
    return r.f;
}
static __device__ __forceinline__ float2 cmul(float2 a, float2 b) {
    return make_float2(fmaf(a.x, b.x, -a.y * b.y), fmaf(a.x, b.y, a.y * b.x));
}
static __device__ __forceinline__ float2 cconj(float2 a) { return make_float2(a.x, -a.y); }

// exp(SGN * i * pi * k / 8), k = 0..7
template <int SGN>
static __device__ __forceinline__ float2 rt16(int k) {
    const float C[8] = {1.f, 0.92387953251f, 0.70710678119f, 0.38268343236f,
                        0.f, -0.38268343236f, -0.70710678119f, -0.92387953251f};
    const float S[8] = {0.f, 0.38268343236f, 0.70710678119f, 0.92387953251f,
                        1.f, 0.92387953251f, 0.70710678119f, 0.38268343236f};
    return make_float2(C[k], (float)SGN * S[k]);
}

// One register round of 4 radix-2 stages on 16 elements.
// Forward (SGN=-1): DIF spans (8,4,2,1)*stride. Inverse (SGN=+1): DIT mirrored.
// TRIV: twiddle base = 1 (compile-time constant roots only).
template <int SGN, bool TRIV>
static __device__ __forceinline__ void fft_round(float2 r[16], float ang) {
    float2 b1;
    if (TRIV) {
        b1 = make_float2(1.f, 0.f);
    } else {
        float sv, cv;
        __sincosf(ang, &sv, &cv);
        b1 = make_float2(cv, SGN < 0 ? -sv : sv);
    }
    float2 b2 = cmul(b1, b1), b4 = cmul(b2, b2), b8 = cmul(b4, b4);
    float2 tw8[8], tw4[4], tw2[2];
#pragma unroll
    for (int k = 0; k < 8; k++) tw8[k] = cmul(b1, rt16<SGN>(k));
#pragma unroll
    for (int k = 0; k < 4; k++) tw4[k] = cmul(b2, rt16<SGN>(2 * k));
    tw2[0] = b4;
    tw2[1] = cmul(b4, make_float2(0.f, (float)SGN));
    if (SGN < 0) {
#pragma unroll
        for (int k = 0; k < 8; k++) { float2 u = r[k], v = r[k + 8]; r[k] = cadd(u, v); r[k + 8] = cmul(csub(u, v), tw8[k]); }
#pragma unroll
        for (int g = 0; g < 16; g += 8)
#pragma unroll
            for (int c = 0; c < 4; c++) { int a = g + c; float2 u = r[a], v = r[a + 4]; r[a] = cadd(u, v); r[a + 4] = cmul(csub(u, v), tw4[c]); }
#pragma unroll
        for (int g = 0; g < 16; g += 4)
#pragma unroll
            for (int c = 0; c < 2; c++) { int a = g + c; float2 u = r[a], v = r[a + 2]; r[a] = cadd(u, v); r[a + 2] = cmul(csub(u, v), tw2[c]); }
#pragma unroll
        for (int a = 0; a < 16; a += 2) { float2 u = r[a], v = r[a + 1]; r[a] = cadd(u, v); r[a + 1] = cmul(csub(u, v), b8); }
    } else {
#pragma unroll
        for (int a = 0; a < 16; a += 2) { float2 v = cmul(r[a + 1], b8), u = r[a]; r[a] = cadd(u, v); r[a + 1] = csub(u, v); }
#pragma unroll
        for (int g = 0; g < 16; g += 4)
#pragma unroll
            for (int c = 0; c < 2; c++) { int a = g + c; float2 v = cmul(r[a + 2], tw2[c]), u = r[a]; r[a] = cadd(u, v); r[a + 2] = csub(u, v); }
#pragma unroll
        for (int g = 0; g < 16; g += 8)
#pragma unroll
            for (int c = 0; c < 4; c++) { int a = g + c; float2 v = cmul(r[a + 4], tw4[c]), u = r[a]; r[a] = cadd(u, v); r[a + 4] = csub(u, v); }
#pragma unroll
        for (int k = 0; k < 8; k++) { float2 v = cmul(r[k + 8], tw8[k]), u = r[k]; r[k] = cadd(u, v); r[k + 8] = csub(u, v); }
    }
}

// Forward 4096-pt DIF (12 stages = 3 rounds), natural -> bit-reversed in smem.
// r preloaded with positions tid + 256k.
static __device__ __forceinline__ void fft4096_fwd(float2* sm, float2 r[16], int tid) {
    fft_round<-1, false>(r, PI_F * (1.0f / 2048.0f) * (float)tid);
#pragma unroll
    for (int k = 0; k < 16; k++) sm[pidx(tid + 256 * k)] = r[k];
    __syncthreads();
    int w = tid & 15, blk = tid >> 4;
#pragma unroll
    for (int k = 0; k < 16; k++) r[k] = sm[pidx(blk * 256 + w + 16 * k)];
    fft_round<-1, false>(r, PI_F * (1.0f / 128.0f) * (float)w);
#pragma unroll
    for (int k = 0; k < 16; k++) sm[pidx(blk * 256 + w + 16 * k)] = r[k];
    __syncthreads();
#pragma unroll
    for (int k = 0; k < 16; k++) r[k] = sm[pidx(tid * 16 + k)];
    fft_round<-1, true>(r, 0.f);
#pragma unroll
    for (int k = 0; k < 16; k++) sm[pidx(tid * 16 + k)] = r[k];
    __syncthreads();
}

// ---------------- K1: (alpha, beta) table per (h, d) ----------------
__global__ __launch_bounds__(256) void k1_spectra(const float* __restrict__ zero,
                                                  const float* __restrict__ pos,
                                                  const float* __restrict__ gamma) {
    __shared__ float2 sm[SMEM_CNT];
    int tid = threadIdx.x;
    int ch = blockIdx.x;          // h*64 + d
    int h = ch >> 6, d = ch & 63;
    float lg = logf(gamma[ch]);
    float z0 = zero[ch];
    float e0 = expf(fminf(fmaxf(z0, -60.f), 30.f));

    float2 r[16];
#pragma unroll
    for (int k = 0; k < 16; k++) {
        int m = tid + 256 * k;
        float v0 = 0.f, v1 = 0.f;
        if (k < 8) {
            int t0 = 2 * m, t1 = 2 * m + 1;
            if (t0 == 0) v0 = e0;
            else {
                float p = pos[((size_t)h * 4095 + (t0 - 1)) * 64 + d];
                v0 = expf(fminf(fmaxf(fmaf((float)t0, lg, p), -60.f), 30.f));
            }
            if (t1 <= 4095) {
                float p = pos[((size_t)h * 4095 + (t1 - 1)) * 64 + d];
                v1 = expf(fminf(fmaxf(fmaf((float)t1, lg, p), -60.f), 30.f));
            }
        } else if (m == 2048) {
            v0 = e0;  // a[4096] = exp(clip(zero))
        }
        r[k] = make_float2(v0, v1);
    }

    fft4096_fwd(sm, r, tid);

    // Unpack real-FFT: A[kf], scaled by 1/32768; keep Nyquist locally (thread m==0).
    const float sc = 1.0f / 32768.0f;
    float2 ar[16];
    float anyq = 0.f;
#pragma unroll
    for (int k = 0; k < 16; k++) {
        int m = tid + 256 * k;
        int kf = __brev(m) >> 20;
        int mp = __brev((4096 - kf) & 4095) >> 20;
        float2 Zm = sm[pidx(m)], Zp = sm[pidx(mp)];
        float2 S = cadd(Zm, cconj(Zp));
        float2 D = csub(Zm, cconj(Zp));
        float sw, cw;
        __sincosf(PI_F * (1.0f / 4096.0f) * (float)kf, &sw, &cw);
        float2 W = make_float2(cw, -sw);
        float2 T = cmul(W, D);
        float2 T2 = make_float2(T.y, -T.x);       // -i*W*D
        float2 Vlo = cadd(S, T2);                 // = 2*A[kf]
        ar[k] = make_float2(Vlo.x * sc, Vlo.y * sc);
        if (m == 0) {
            float2 Vhi = csub(S, T2);             // = 2*A[4096] (real)
            anyq = Vhi.x * sc;
        }
    }
    __syncthreads();
#pragma unroll
    for (int k = 0; k < 16; k++) sm[pidx(tid + 256 * k)] = ar[k];
    __syncthreads();

    // alpha/beta: Z'[m] = alpha*Z[m] + beta*conj(Z[mp])
    //   alpha = (2-2s)*Alo + (2+2s)*Ahi,  beta = 2i*c*(Alo - Ahi)
    //   with W = exp(-i*pi*kf/4096) = (c, -s); Alo = A[kf]; Ahi = conj(A[4096-kf]) (m=0: Anyq)
    float4* ab = g_AB + (size_t)ch * 4096;
#pragma unroll
    for (int k = 0; k < 16; k++) {
        int m = tid + 256 * k;
        int kf = __brev(m) >> 20;
        int mp = __brev((4096 - kf) & 4095) >> 20;
        float2 Alo = sm[pidx(m)];
        float2 Ahi = (m == 0) ? make_float2(anyq, 0.f) : cconj(sm[pidx(mp)]);
        float sw, cw;
        __sincosf(PI_F * (1.0f / 4096.0f) * (float)kf, &sw, &cw);
        float ca = 2.f - 2.f * sw, cb = 2.f + 2.f * sw, cc = 2.f * cw;
        float2 alpha = make_float2(ca * Alo.x + cb * Ahi.x, ca * Alo.y + cb * Ahi.y);
        float2 dif = csub(Alo, Ahi);
        float2 beta = make_float2(-cc * dif.y, cc * dif.x);
        ab[m] = make_float4(alpha.x, alpha.y, beta.x, beta.y);
    }
}

// ---------------- K2: x [bh][t][d] -> g_xt [bh][d][t] ----------------
__global__ void k2_transpose(const float* __restrict__ x) {
    __shared__ float tile[32][33];
    int bh = blockIdx.z;
    int t0 = blockIdx.x << 5, d0 = blockIdx.y << 5;
    const float* xp = x + (size_t)bh * (4096 * 64);
    float* xtp = g_xt + (size_t)bh * (64 * 4096);
    int tx = threadIdx.x, ty = threadIdx.y;
#pragma unroll
    for (int j = 0; j < 32; j += 8) tile[ty + j][tx] = xp[(size_t)(t0 + ty + j) * 64 + d0 + tx];
    __syncthreads();
#pragma unroll
    for (int j = 0; j < 32; j += 8) xtp[(size_t)(d0 + ty + j) * 4096 + t0 + tx] = tile[tx][ty + j];
}

// ---------------- K3: per (bh, d) real FFT conv via packed 4096-pt complex FFT ----------------
__global__ __launch_bounds__(256, 3) void k3_fftconv() {
    __shared__ float2 sm[SMEM_CNT];
    int tid = threadIdx.x;
    int bhd = blockIdx.x;                 // bh*64 + d
    int ch = ((bhd >> 6) & 7) * 64 + (bhd & 63);  // (h, d) channel for table
    float2* row = (float2*)(g_xt + (size_t)bhd * 4096);

    float2 r[16];
#pragma unroll
    for (int k = 0; k < 8; k++) r[k] = row[tid + 256 * k];      // z[m]=u[2m]+i u[2m+1]
#pragma unroll
    for (int k = 8; k < 16; k++) r[k] = make_float2(0.f, 0.f);  // zero padding

    fft4096_fwd(sm, r, tid);

    // MID: Z'[m] = alpha*Z[m] + beta*conj(Z[mp]); all unpack/scale folded into table.
    const float4* abp = g_AB + (size_t)ch * 4096;
#pragma unroll
    for (int k = 0; k < 16; k++) {
        int m = tid + 256 * k;
        int kf = __brev(m) >> 20;
        int mp = __brev((4096 - kf) & 4095) >> 20;
        float2 Zm = sm[pidx(m)], Zp = sm[pidx(mp)];
        float4 ab = abp[m];
        float2 t1 = cmul(Zm, make_float2(ab.x, ab.y));
        float2 t2 = cmul(cconj(Zp), make_float2(ab.z, ab.w));
        r[k] = cadd(t1, t2);
    }
    __syncthreads();
#pragma unroll
    for (int k = 0; k < 16; k++) sm[pidx(tid + 256 * k)] = r[k];
    __syncthreads();

    // Inverse DIT (bit-rev -> natural), mirrored rounds.
#pragma unroll
    for (int k = 0; k < 16; k++) r[k] = sm[pidx(tid * 16 + k)];
    fft_round<1, true>(r, 0.f);
#pragma unroll
    for (int k = 0; k < 16; k++) sm[pidx(tid * 16 + k)] = r[k];
    __syncthreads();
    int w = tid & 15, blk = tid >> 4;
#pragma unroll
    for (int k = 0; k < 16; k++) r[k] = sm[pidx(blk * 256 + w + 16 * k)];
    fft_round<1, false>(r, PI_F * (1.0f / 128.0f) * (float)w);
#pragma unroll
    for (int k = 0; k < 16; k++) sm[pidx(blk * 256 + w + 16 * k)] = r[k];
    __syncthreads();
#pragma unroll
    for (int k = 0; k < 16; k++) r[k] = sm[pidx(tid + 256 * k)];
    fft_round<1, false>(r, PI_F * (1.0f / 2048.0f) * (float)tid);
#pragma unroll
    for (int k = 0; k < 8; k++) row[tid + 256 * k] = r[k];   // y[2m], y[2m+1]; t<4096 only
}

// ---------------- K4: g_xt (y) [bh][d][t] -> out [bh][t][d] ----------------
__global__ void k4_transpose(float* __restrict__ out) {
    __shared__ float tile[32][33];
    int bh = blockIdx.z;
    int t0 = blockIdx.x << 5, d0 = blockIdx.y << 5;
    const float* ytp = g_xt + (size_t)bh * (64 * 4096);
    float* op = out + (size_t)bh * (4096 * 64);
    int tx = threadIdx.x, ty = threadIdx.y;
#pragma unroll
    for (int j = 0; j < 32; j += 8) tile[ty + j][tx] = ytp[(size_t)(d0 + ty + j) * 4096 + t0 + tx];
    __syncthreads();
#pragma unroll
    for (int j = 0; j < 32; j += 8) op[(size_t)(t0 + ty + j) * 64 + d0 + tx] = tile[tx][ty + j];
}

extern "C" void kernel_launch(void* const* d_in, const int* in_sizes, int n_in,
                              void* d_out, int out_size) {
    (void)in_sizes; (void)n_in; (void)out_size;
    const float* x     = (const float*)d_in[0];
    const float* zero  = (const float*)d_in[1];
    const float* pos   = (const float*)d_in[2];
    const float* gamma = (const float*)d_in[3];
    float* out = (float*)d_out;

    k1_spectra<<<512, 256>>>(zero, pos, gamma);
    dim3 tb(32, 8);
    k2_transpose<<<dim3(128, 2, 64), tb>>>(x);
    k3_fftconv<<<4096, 256>>>();
    k4_transpose<<<dim3(128, 2, 64), tb>>>(out);
}